// round 14
// baseline (speedup 1.0000x reference)
#include <cuda_runtime.h>
#include <cstddef>

#define IMH 1024
#define IMW 1024
#define SFRAMES 8
#define NB 4
#define TR 32            // tile rows (output)
#define TC 64            // tile cols
#define NTHREADS 256
#define GH (TR + 8)      // 40 rows incl vertical halo
#define GWF (TC + 8)     // 72: gray tile width incl horizontal halo (floats)
#define NT4 (GH * (GWF / 4))   // 720 float4 gray-load tasks (18 per row)
#define NHT (GH * (TC / 4))    // 640 hconv tasks
#define HABSZ (GH * TC * 2)    // 5120 floats per sHAB buffer

// smem layout (floats): sG[GH*GWF] | sHAB0[HABSZ] | sHAB1[HABSZ]
#define SMEM_FLOATS (GH * GWF + 2 * HABSZ)
#define SMEM_BYTES  (SMEM_FLOATS * 4)      // 52,480 B -> 4 CTAs/SM

__device__ __forceinline__ int reflect101(int i, int n) {
    if (i < 0) i = -i;
    if (i >= n) i = 2 * n - 2 - i;
    return i;
}

// ============================================================================
// Fused: 8-frame laplacian-of-gaussian + argmax + L1-hot winner RGB tracking
//  P1: flat high-MLP gray load -> sG        (R12, proven)
//  P2: hconv from sG -> interleaved sHAB (double-buffered)
//  P3: vertical 9-tap, 8-row x 1-col, 16-row float2 stream (16 B/px)
//  2 block barriers per frame (double buffer removes the tail barrier).
// ============================================================================
extern "C" __global__ void __launch_bounds__(NTHREADS, 4)
lap_merge_kernel(const float* __restrict__ x, float* __restrict__ out)
{
    extern __shared__ float smem[];
    float* sG = smem;                       // GH x GWF gray (+halo)

    const int tid = threadIdx.x;
    const int b   = blockIdx.z;
    const int hr0 = blockIdx.y * TR;
    const int wc0 = blockIdx.x * TC;
    const size_t HW = (size_t)IMH * IMW;
    const float ONE3 = 0.33333334f;
    const bool interior = (blockIdx.x != 0) && ((int)blockIdx.x != (int)gridDim.x - 1);

    // per-thread state: 8 px = 8 rows x 1 col
    const int r0  = (tid >> 6) * 8;         // 4 row-groups x 8 rows = 32 rows
    const int col = tid & 63;               // 64 cols

    float bestLap[8], bR[8], bG[8], bB[8];
#pragma unroll
    for (int rr = 0; rr < 8; rr++) bestLap[rr] = -3.0e38f;

    for (int s = 0; s < SFRAMES; s++) {
        const float* __restrict__ xf = x + ((size_t)(b * SFRAMES + s)) * 3 * HW;
        float* __restrict__ sHAB = smem + GH * GWF + (s & 1) * HABSZ;

        // ==== Phase 1: gray tile load (flat, high-MLP) ====
        if (interior) {
#pragma unroll
            for (int k = 0; k < 3; k++) {
                const int t = tid + k * NTHREADS;
                if (t < NT4) {
                    const int r  = t / (GWF / 4);
                    const int c4 = t - r * (GWF / 4);
                    const int gr = reflect101(hr0 - 4 + r, IMH);
                    const float* __restrict__ p = xf + (size_t)gr * IMW + (wc0 - 4 + c4 * 4);
                    float4 a  = *reinterpret_cast<const float4*>(p);
                    float4 bq = *reinterpret_cast<const float4*>(p + HW);
                    float4 c  = *reinterpret_cast<const float4*>(p + 2 * HW);
                    float4 g;
                    g.x = (a.x + bq.x + c.x) * ONE3;
                    g.y = (a.y + bq.y + c.y) * ONE3;
                    g.z = (a.z + bq.z + c.z) * ONE3;
                    g.w = (a.w + bq.w + c.w) * ONE3;
                    *reinterpret_cast<float4*>(&sG[r * GWF + c4 * 4]) = g;
                }
            }
        } else {
            for (int i = tid; i < GH * GWF; i += NTHREADS) {
                const int r = i / GWF;
                const int c = i - r * GWF;
                const int gr = reflect101(hr0 - 4 + r, IMH);
                const int gc = reflect101(wc0 - 4 + c, IMW);
                const float* __restrict__ p = xf + (size_t)gr * IMW + gc;
                sG[i] = (__ldg(p) + __ldg(p + HW) + __ldg(p + 2 * HW)) * ONE3;
            }
        }
        __syncthreads();                    // B1: sG ready (also orders P3(s-1) before P2(s+1))

        // ==== Phase 2: horizontal 9-tap A/B from sG -> interleaved sHAB ====
#pragma unroll
        for (int k = 0; k < 3; k++) {
            const int t = tid + k * NTHREADS;
            if (t < NHT) {
                const int r  = t / (TC / 4);
                const int c2 = t - r * (TC / 4);
                float w[12];
#pragma unroll
                for (int j = 0; j < 12; j += 4)
                    *reinterpret_cast<float4*>(&w[j]) =
                        *reinterpret_cast<const float4*>(&sG[r * GWF + c2 * 4 + j]);
                float4 hA4, hB4;
#pragma unroll
                for (int o = 0; o < 4; o++) {
                    float p1 = w[o + 3] + w[o + 5];
                    float p2 = w[o + 2] + w[o + 6];
                    float p3 = w[o + 1] + w[o + 7];
                    float p4 = w[o + 0] + w[o + 8];
                    float ctr = w[o + 4];
                    (&hA4.x)[o] =  4.375f * ctr + 3.5f  * p1 + 1.75f * p2 + 0.5f  * p3 + 0.0625f * p4;
                    (&hB4.x)[o] = -0.625f * ctr - 0.25f * p1 + 0.25f * p2 + 0.25f * p3 + 0.0625f * p4;
                }
                float* dst = &sHAB[(r * TC + c2 * 4) * 2];
                *reinterpret_cast<float4*>(dst)     = make_float4(hA4.x, hB4.x, hA4.y, hB4.y);
                *reinterpret_cast<float4*>(dst + 4) = make_float4(hA4.z, hB4.z, hA4.w, hB4.w);
            }
        }
        __syncthreads();                    // B2: sHAB ready (also releases sG for next P1)

        // ==== Phase 3: vertical 9-tap (B on hA + A on hB), 16-row stream + argmax ====
        {
            const float wAv[9] = {0.0625f, 0.5f, 1.75f, 3.5f, 4.375f, 3.5f, 1.75f, 0.5f, 0.0625f};
            const float wBv[9] = {0.0625f, 0.25f, 0.25f, -0.25f, -0.625f, -0.25f, 0.25f, 0.25f, 0.0625f};
            float acc[8];
#pragma unroll
            for (int rr = 0; rr < 8; rr++) acc[rr] = 0.f;

#pragma unroll
            for (int j = 0; j < 16; j++) {
                const float2 v = *reinterpret_cast<const float2*>(
                    &sHAB[((r0 + j) * TC + col) * 2]);
#pragma unroll
                for (int rr = 0; rr < 8; rr++) {
                    const int jj = j - rr;
                    if (jj >= 0 && jj <= 8) {    // static after unroll
                        acc[rr] += wBv[jj] * v.x + wAv[jj] * v.y;
                    }
                }
            }
#pragma unroll
            for (int rr = 0; rr < 8; rr++) {
                if (acc[rr] > bestLap[rr]) {     // strict > == first-max (jnp.argmax)
                    bestLap[rr] = acc[rr];
                    // winner RGB reload: bytes just read by P1 -> L1 hit
                    const float* __restrict__ xw =
                        xf + (size_t)(hr0 + r0 + rr) * IMW + (wc0 + col);
                    bR[rr] = __ldg(xw);
                    bG[rr] = __ldg(xw + HW);
                    bB[rr] = __ldg(xw + 2 * HW);
                }
            }
        }
        // no tail barrier: double-buffered sHAB + barrier chain covers reuse
    }

    // ==== Epilogue: write winner RGB (b, c, h, w) ====
#pragma unroll
    for (int rr = 0; rr < 8; rr++) {
        const size_t obase = ((size_t)(b * 3) * IMH + (hr0 + r0 + rr)) * IMW + wc0 + col;
        out[obase]          = bR[rr];
        out[obase + HW]     = bG[rr];
        out[obase + 2 * HW] = bB[rr];
    }
}

// ============================================================================
extern "C" void kernel_launch(void* const* d_in, const int* in_sizes, int n_in,
                              void* d_out, int out_size)
{
    const float* x = (const float*)d_in[0];
    float* out = (float*)d_out;

    cudaFuncSetAttribute(lap_merge_kernel,
                         cudaFuncAttributeMaxDynamicSharedMemorySize, SMEM_BYTES);

    dim3 grid(IMW / TC, IMH / TR, NB);
    lap_merge_kernel<<<grid, NTHREADS, SMEM_BYTES>>>(x, out);
}